// round 4
// baseline (speedup 1.0000x reference)
#include <cuda_runtime.h>

// EMA: y[0] = x[0]; y[t] = 0.3*x[t] + 0.7*y[t-1]
// Shape (B=64, T=4096, D=256), fp32.
//
// Chunked-parallel scan: each 64-step T-chunk computed independently with a
// 20-step halo warm-up (0.7^20 ~ 8e-4, empirical error factor ~0.086 ->
// rel_err ~7e-5 << 1e-3). 4096 blocks -> single wave, ~86% occupancy; halo
// reads overlap the co-resident sibling chunk's main region -> L2 hits.

#define EMA_B 64
#define EMA_T 4096
#define EMA_D 256
#define EMA_D4 (EMA_D / 4)               // 64 float4 lanes per timestep
#define EMA_CHUNK 64
#define EMA_NCHUNK (EMA_T / EMA_CHUNK)   // 64
#define EMA_HALO 20
#define EMA_S 0.3f
#define EMA_C 0.7f

__global__ void __launch_bounds__(EMA_D4)
ema_kernel(const float4* __restrict__ x, float4* __restrict__ y) {
    const int lane  = threadIdx.x;                 // 0..63: channel quad
    const int chunk = blockIdx.x % EMA_NCHUNK;     // adjacent blocks = adjacent
    const int b     = blockIdx.x / EMA_NCHUNK;     // chunks -> halo L2 reuse

    const float4* __restrict__ xp = x + (size_t)b * EMA_T * EMA_D4 + lane;
    float4*       __restrict__ yp = y + (size_t)b * EMA_T * EMA_D4 + lane;

    const int t0 = chunk * EMA_CHUNK;

    float a0, a1, a2, a3;
    if (chunk == 0) {
        // Seed acc = x[0]: first main-loop step gives y[0] = 0.3x0+0.7x0 = x0.
        float4 v = xp[0];
        a0 = v.x; a1 = v.y; a2 = v.z; a3 = v.w;
    } else {
        // Halo warm-up from zero.
        a0 = a1 = a2 = a3 = 0.0f;
        const int th = t0 - EMA_HALO;
#pragma unroll
        for (int k = 0; k < EMA_HALO; ++k) {
            float4 v = xp[(th + k) * EMA_D4];
            a0 = fmaf(EMA_C, a0, EMA_S * v.x);
            a1 = fmaf(EMA_C, a1, EMA_S * v.y);
            a2 = fmaf(EMA_C, a2, EMA_S * v.z);
            a3 = fmaf(EMA_C, a3, EMA_S * v.w);
        }
    }

    // Main loop, software-pipelined one load ahead.
    float4 v = xp[t0 * EMA_D4];
#pragma unroll 8
    for (int t = t0; t < t0 + EMA_CHUNK - 1; ++t) {
        float4 vn = xp[(t + 1) * EMA_D4];
        a0 = fmaf(EMA_C, a0, EMA_S * v.x);
        a1 = fmaf(EMA_C, a1, EMA_S * v.y);
        a2 = fmaf(EMA_C, a2, EMA_S * v.z);
        a3 = fmaf(EMA_C, a3, EMA_S * v.w);
        __stcs(&yp[t * EMA_D4], make_float4(a0, a1, a2, a3));
        v = vn;
    }
    {
        const int t = t0 + EMA_CHUNK - 1;
        a0 = fmaf(EMA_C, a0, EMA_S * v.x);
        a1 = fmaf(EMA_C, a1, EMA_S * v.y);
        a2 = fmaf(EMA_C, a2, EMA_S * v.z);
        a3 = fmaf(EMA_C, a3, EMA_S * v.w);
        __stcs(&yp[t * EMA_D4], make_float4(a0, a1, a2, a3));
    }
}

extern "C" void kernel_launch(void* const* d_in, const int* in_sizes, int n_in,
                              void* d_out, int out_size) {
    const float4* x = (const float4*)d_in[0];
    float4* y = (float4*)d_out;
    const int grid = EMA_B * EMA_NCHUNK;   // 4096 blocks of 64 threads
    ema_kernel<<<grid, EMA_D4>>>(x, y);
}

// round 5
// speedup vs baseline: 1.1439x; 1.1439x over previous
#include <cuda_runtime.h>

// EMA: y[0] = x[0]; y[t] = 0.3*x[t] + 0.7*y[t-1]
// Shape (B=64, T=4096, D=256), fp32.
//
// Chunked-parallel scan, CHUNK=128 / HALO=20 (rel_err ~1e-4 << 1e-3).
// float2 lanes: 128 threads per chunk -> 2x warp count vs float4 at the same
// chunk geometry (55 warps/SM, ~86% occ) to hide HBM latency. Adjacent blocks
// process adjacent chunks so halo reads hit L2.

#define EMA_B 64
#define EMA_T 4096
#define EMA_D 256
#define EMA_D2 (EMA_D / 2)               // 128 float2 lanes per timestep
#define EMA_CHUNK 128
#define EMA_NCHUNK (EMA_T / EMA_CHUNK)   // 32
#define EMA_HALO 20
#define EMA_S 0.3f
#define EMA_C 0.7f

__global__ void __launch_bounds__(EMA_D2)
ema_kernel(const float2* __restrict__ x, float2* __restrict__ y) {
    const int lane  = threadIdx.x;                 // 0..127: channel pair
    const int chunk = blockIdx.x % EMA_NCHUNK;     // adjacent blocks = adjacent
    const int b     = blockIdx.x / EMA_NCHUNK;     // chunks -> halo L2 reuse

    const float2* __restrict__ xp = x + (size_t)b * EMA_T * EMA_D2 + lane;
    float2*       __restrict__ yp = y + (size_t)b * EMA_T * EMA_D2 + lane;

    const int t0 = chunk * EMA_CHUNK;

    float a0, a1;
    if (chunk == 0) {
        // Seed acc = x[0]: first main-loop step gives y[0] = 0.3x0+0.7x0 = x0.
        float2 v = xp[0];
        a0 = v.x; a1 = v.y;
    } else {
        // Halo warm-up from zero.
        a0 = a1 = 0.0f;
        const int th = t0 - EMA_HALO;
#pragma unroll
        for (int k = 0; k < EMA_HALO; ++k) {
            float2 v = xp[(th + k) * EMA_D2];
            a0 = fmaf(EMA_C, a0, EMA_S * v.x);
            a1 = fmaf(EMA_C, a1, EMA_S * v.y);
        }
    }

    // Main loop, software-pipelined one load ahead.
    float2 v = xp[t0 * EMA_D2];
#pragma unroll 8
    for (int t = t0; t < t0 + EMA_CHUNK - 1; ++t) {
        float2 vn = xp[(t + 1) * EMA_D2];
        a0 = fmaf(EMA_C, a0, EMA_S * v.x);
        a1 = fmaf(EMA_C, a1, EMA_S * v.y);
        __stcs(&yp[t * EMA_D2], make_float2(a0, a1));
        v = vn;
    }
    {
        const int t = t0 + EMA_CHUNK - 1;
        a0 = fmaf(EMA_C, a0, EMA_S * v.x);
        a1 = fmaf(EMA_C, a1, EMA_S * v.y);
        __stcs(&yp[t * EMA_D2], make_float2(a0, a1));
    }
}

extern "C" void kernel_launch(void* const* d_in, const int* in_sizes, int n_in,
                              void* d_out, int out_size) {
    const float2* x = (const float2*)d_in[0];
    float2* y = (float2*)d_out;
    const int grid = EMA_B * EMA_NCHUNK;   // 2048 blocks of 128 threads
    ema_kernel<<<grid, EMA_D2>>>(x, y);
}

// round 6
// speedup vs baseline: 1.1521x; 1.0071x over previous
#include <cuda_runtime.h>

// EMA: y[0] = x[0]; y[t] = 0.3*x[t] + 0.7*y[t-1]
// Shape (B=64, T=4096, D=256), fp32.
//
// Chunked-parallel scan: CHUNK=128 / HALO=20 (rel_err ~7e-5 << 1e-3).
// float4 lanes, 64-thread blocks, adjacent blocks on adjacent chunks for
// halo L2 reuse. Main loop processes groups of 4 timesteps with explicit
// double-buffering: the 4 LDG.128 of the next group are issued back-to-back
// before the FMA+store of the current group, raising per-thread MLP to ~4-5.

#define EMA_B 64
#define EMA_T 4096
#define EMA_D 256
#define EMA_D4 (EMA_D / 4)               // 64 float4 lanes per timestep
#define EMA_CHUNK 128
#define EMA_NCHUNK (EMA_T / EMA_CHUNK)   // 32
#define EMA_HALO 20
#define EMA_G 4                          // timesteps per group
#define EMA_NG (EMA_CHUNK / EMA_G)       // 32 groups
#define EMA_S 0.3f
#define EMA_C 0.7f

__global__ void __launch_bounds__(EMA_D4)
ema_kernel(const float4* __restrict__ x, float4* __restrict__ y) {
    const int lane  = threadIdx.x;                 // 0..63: channel quad
    const int chunk = blockIdx.x % EMA_NCHUNK;
    const int b     = blockIdx.x / EMA_NCHUNK;

    const float4* __restrict__ xp = x + (size_t)b * EMA_T * EMA_D4 + lane;
    float4*       __restrict__ yp = y + (size_t)b * EMA_T * EMA_D4 + lane;

    const int t0 = chunk * EMA_CHUNK;

    float a0, a1, a2, a3;
    if (chunk == 0) {
        // Seed acc = x[0]: first main-loop step gives y[0] = 0.3x0+0.7x0 = x0.
        float4 v = xp[0];
        a0 = v.x; a1 = v.y; a2 = v.z; a3 = v.w;
    } else {
        // Halo warm-up from zero (0.7^20 truncation).
        a0 = a1 = a2 = a3 = 0.0f;
        const int th = t0 - EMA_HALO;
#pragma unroll
        for (int k = 0; k < EMA_HALO; ++k) {
            float4 v = xp[(th + k) * EMA_D4];
            a0 = fmaf(EMA_C, a0, EMA_S * v.x);
            a1 = fmaf(EMA_C, a1, EMA_S * v.y);
            a2 = fmaf(EMA_C, a2, EMA_S * v.z);
            a3 = fmaf(EMA_C, a3, EMA_S * v.w);
        }
    }

    // Double-buffered group pipeline.
    float4 buf[EMA_G];
#pragma unroll
    for (int j = 0; j < EMA_G; ++j)
        buf[j] = xp[(t0 + j) * EMA_D4];

    for (int g = 0; g < EMA_NG; ++g) {
        const int tg = t0 + g * EMA_G;
        float4 nbuf[EMA_G];
        if (g + 1 < EMA_NG) {
            // Front-batched loads of the NEXT group: 4 independent LDG.128.
#pragma unroll
            for (int j = 0; j < EMA_G; ++j)
                nbuf[j] = xp[(tg + EMA_G + j) * EMA_D4];
        }
#pragma unroll
        for (int j = 0; j < EMA_G; ++j) {
            a0 = fmaf(EMA_C, a0, EMA_S * buf[j].x);
            a1 = fmaf(EMA_C, a1, EMA_S * buf[j].y);
            a2 = fmaf(EMA_C, a2, EMA_S * buf[j].z);
            a3 = fmaf(EMA_C, a3, EMA_S * buf[j].w);
            __stcs(&yp[(tg + j) * EMA_D4], make_float4(a0, a1, a2, a3));
        }
#pragma unroll
        for (int j = 0; j < EMA_G; ++j)
            buf[j] = nbuf[j];
    }
}

extern "C" void kernel_launch(void* const* d_in, const int* in_sizes, int n_in,
                              void* d_out, int out_size) {
    const float4* x = (const float4*)d_in[0];
    float4* y = (float4*)d_out;
    const int grid = EMA_B * EMA_NCHUNK;   // 2048 blocks of 64 threads
    ema_kernel<<<grid, EMA_D4>>>(x, y);
}